// round 1
// baseline (speedup 1.0000x reference)
#include <cuda_runtime.h>
#include <math.h>

#define DIN   784
#define DH    512
#define DOUT  10
#define BATCH 256

#define BM 64
#define BN 64
#define BK 16
#define KSPLIT 4
#define KCH (DIN / KSPLIT)   // 196

// ---------------- device scratch (no allocations allowed) ----------------
__device__ __align__(16) float g_pmu[KSPLIT * BATCH * DH];
__device__ __align__(16) float g_pq [KSPLIT * BATCH * DH];
__device__ __align__(16) float g_m2 [BATCH * DH];
__device__ __align__(16) float g_s2 [BATCH * DH];
__device__ __align__(16) float g_Ws2[DOUT * DH];
__device__ float g_spb1[DH];
__device__ float g_spb2[DOUT];
__device__ float g_klpart[256];

__device__ __forceinline__ float softplus_ref(float x) {
    // matches jnp.log(1.0 + jnp.exp(x))
    return logf(1.0f + expf(x));
}

// ---------------- K0: softplus precompute + KL block partials ----------------
__global__ void k0_prep(const float* __restrict__ w_mu1,
                        const float* __restrict__ w_sigma1,
                        const float* __restrict__ b_sigma1,
                        const float* __restrict__ w_mu2,
                        const float* __restrict__ w_sigma2,
                        const float* __restrict__ b_sigma2) {
    const int T = gridDim.x * blockDim.x;
    const int gtid = blockIdx.x * blockDim.x + threadIdx.x;
    float acc = 0.f;
    for (int i = gtid; i < DH * DIN; i += T) {
        float sp = softplus_ref(w_sigma1[i]);
        acc += sp - logf(sp);
    }
    for (int i = gtid; i < DIN * DH; i += T) {
        float v = w_mu1[i];
        acc += v * v;
    }
    for (int i = gtid; i < DOUT * DH; i += T) {
        float sp = softplus_ref(w_sigma2[i]);
        g_Ws2[i] = sp;
        acc += sp - logf(sp);
    }
    for (int i = gtid; i < DH * DOUT; i += T) {
        float v = w_mu2[i];
        acc += v * v;
    }
    if (gtid < DH)   g_spb1[gtid] = softplus_ref(b_sigma1[gtid]);
    if (gtid < DOUT) g_spb2[gtid] = softplus_ref(b_sigma2[gtid]);

    // deterministic block reduce
    __shared__ float red[8];
    #pragma unroll
    for (int s = 16; s; s >>= 1) acc += __shfl_xor_sync(0xffffffffu, acc, s);
    int warp = threadIdx.x >> 5, lane = threadIdx.x & 31;
    if (lane == 0) red[warp] = acc;
    __syncthreads();
    if (threadIdx.x == 0) {
        float t = 0.f;
        #pragma unroll
        for (int w = 0; w < 8; w++) t += red[w];
        g_klpart[blockIdx.x] = t;
    }
}

// ---------------- K1: layer-1 dual GEMM (mu1 + quad1), split-K ----------------
// mu1_part[b,h]  = sum_k x[b,k]   * w_mu1[k,h]
// q_part [b,h]   = sum_k x[b,k]^2 * softplus(w_sigma1[h,k])
__global__ __launch_bounds__(256) void k1_gemm(const float* __restrict__ x,
                                               const float* __restrict__ w_mu1,
                                               const float* __restrict__ w_sigma1) {
    __shared__ __align__(16) float As [BK][68];   // [k][b], padded
    __shared__ __align__(16) float B1s[BK][68];   // [k][h]
    __shared__ __align__(16) float B2s[BK][68];   // [k][h] (softplus applied)

    const int n0 = blockIdx.x * BN;
    const int b0 = blockIdx.y * BM;
    const int ks = blockIdx.z;
    const int kstart = ks * KCH;
    const int kend   = kstart + KCH;

    const int tid = threadIdx.x;
    const int tx = tid & 15, ty = tid >> 4;   // compute microtile coords
    const int ar = tid >> 2, ac = tid & 3;    // A / B2 load coords (row 0..63, k-quad 0..3)
    const int bk = tid >> 4, bn = tid & 15;   // B1 load coords

    float amu[4][4] = {}, aq[4][4] = {};

    for (int k0 = kstart; k0 < kend; k0 += BK) {
        // A tile (and transpose into [k][b]); quad granularity is safe: KCH % 4 == 0
        {
            int k = k0 + ac * 4;
            float4 v = make_float4(0.f, 0.f, 0.f, 0.f);
            if (k < kend) v = *(const float4*)&x[(b0 + ar) * DIN + k];
            As[ac * 4 + 0][ar] = v.x;
            As[ac * 4 + 1][ar] = v.y;
            As[ac * 4 + 2][ar] = v.z;
            As[ac * 4 + 3][ar] = v.w;
        }
        // B1 tile (w_mu1 is [k][h], naturally n-contiguous)
        {
            int k = k0 + bk;
            float4 v = make_float4(0.f, 0.f, 0.f, 0.f);
            if (k < kend) v = *(const float4*)&w_mu1[k * DH + n0 + bn * 4];
            *(float4*)&B1s[bk][bn * 4] = v;
        }
        // B2 tile: softplus(w_sigma1[h][k]) transposed into [k][h]
        {
            int k = k0 + ac * 4;
            float4 v = make_float4(0.f, 0.f, 0.f, 0.f);
            if (k < kend) {
                float4 r = *(const float4*)&w_sigma1[(n0 + ar) * DIN + k];
                v.x = softplus_ref(r.x);
                v.y = softplus_ref(r.y);
                v.z = softplus_ref(r.z);
                v.w = softplus_ref(r.w);
            }
            B2s[ac * 4 + 0][ar] = v.x;
            B2s[ac * 4 + 1][ar] = v.y;
            B2s[ac * 4 + 2][ar] = v.z;
            B2s[ac * 4 + 3][ar] = v.w;
        }
        __syncthreads();

        #pragma unroll
        for (int kk = 0; kk < BK; kk++) {
            float4 a  = *(const float4*)&As [kk][ty * 4];
            float4 b1 = *(const float4*)&B1s[kk][tx * 4];
            float4 b2 = *(const float4*)&B2s[kk][tx * 4];
            float av[4]  = {a.x, a.y, a.z, a.w};
            float b1v[4] = {b1.x, b1.y, b1.z, b1.w};
            float b2v[4] = {b2.x, b2.y, b2.z, b2.w};
            #pragma unroll
            for (int i = 0; i < 4; i++) {
                float ai = av[i];
                float a2 = ai * ai;
                #pragma unroll
                for (int j = 0; j < 4; j++) {
                    amu[i][j] += ai * b1v[j];
                    aq [i][j] += a2 * b2v[j];
                }
            }
        }
        __syncthreads();
    }

    #pragma unroll
    for (int i = 0; i < 4; i++) {
        int b = b0 + ty * 4 + i;
        float4 m = make_float4(amu[i][0], amu[i][1], amu[i][2], amu[i][3]);
        float4 q = make_float4(aq [i][0], aq [i][1], aq [i][2], aq [i][3]);
        *(float4*)&g_pmu[(ks * BATCH + b) * DH + n0 + tx * 4] = m;
        *(float4*)&g_pq [(ks * BATCH + b) * DH + n0 + tx * 4] = q;
    }
}

// ---------------- K1b: combine split-K partials + bias + ReLU epilogue ----------------
__global__ void k1b_combine(const float* __restrict__ b_mu1) {
    const int S = BATCH * DH;
    int i4 = blockIdx.x * blockDim.x + threadIdx.x;  // one float4 per thread
    int base = i4 * 4;
    if (base >= S) return;
    int h = base & (DH - 1);

    float4 m0 = *(const float4*)&g_pmu[0 * S + base];
    float4 m1 = *(const float4*)&g_pmu[1 * S + base];
    float4 m2 = *(const float4*)&g_pmu[2 * S + base];
    float4 m3 = *(const float4*)&g_pmu[3 * S + base];
    float4 q0 = *(const float4*)&g_pq [0 * S + base];
    float4 q1 = *(const float4*)&g_pq [1 * S + base];
    float4 q2 = *(const float4*)&g_pq [2 * S + base];
    float4 q3 = *(const float4*)&g_pq [3 * S + base];

    float mu[4] = {((m0.x + m1.x) + m2.x) + m3.x,
                   ((m0.y + m1.y) + m2.y) + m3.y,
                   ((m0.z + m1.z) + m2.z) + m3.z,
                   ((m0.w + m1.w) + m2.w) + m3.w};
    float qq[4] = {((q0.x + q1.x) + q2.x) + q3.x,
                   ((q0.y + q1.y) + q2.y) + q3.y,
                   ((q0.z + q1.z) + q2.z) + q3.z,
                   ((q0.w + q1.w) + q2.w) + q3.w};

    float4 om, os;
    float* pm = (float*)&om;
    float* pq = (float*)&os;
    #pragma unroll
    for (int j = 0; j < 4; j++) {
        float m = mu[j] + b_mu1[h + j];
        bool g = (m > 0.f);
        pm[j] = g ? m : 0.f;
        pq[j] = g ? (qq[j] + g_spb1[h + j]) : 0.f;
    }
    *(float4*)&g_m2[base] = om;
    *(float4*)&g_s2[base] = os;
}

// ---------------- K2: layer 2 + softmax + Jacobian sandwich (1 block per batch) ----------------
__global__ __launch_bounds__(256) void k2_layer2(const float* __restrict__ w_mu2,
                                                 const float* __restrict__ b_mu2,
                                                 float* __restrict__ out) {
    __shared__ float m2s[DH], s2s[DH];
    __shared__ float wsm[DH * DOUT];
    __shared__ float mus[DOUT], qus[DOUT], ps[DOUT], qv[DOUT], rr[DOUT];
    __shared__ float sig[DOUT * DOUT], t1[DOUT * DOUT];
    __shared__ float redm[8][DOUT], redq[8][DOUT];

    const int b = blockIdx.x, tid = threadIdx.x;

    for (int i = tid; i < DH; i += 256) {
        m2s[i] = g_m2[b * DH + i];
        s2s[i] = g_s2[b * DH + i];
    }
    for (int i = tid; i < DH * DOUT; i += 256) wsm[i] = w_mu2[i];
    __syncthreads();

    // mu3 and quad2 partials
    float amu[DOUT], aq[DOUT];
    #pragma unroll
    for (int o = 0; o < DOUT; o++) { amu[o] = 0.f; aq[o] = 0.f; }
    for (int h = tid; h < DH; h += 256) {
        float m = m2s[h], ms = m * m;
        #pragma unroll
        for (int o = 0; o < DOUT; o++) {
            amu[o] += wsm[h * DOUT + o] * m;
            aq [o] += g_Ws2[o * DH + h] * ms;
        }
    }
    #pragma unroll
    for (int o = 0; o < DOUT; o++) {
        #pragma unroll
        for (int s = 16; s; s >>= 1) {
            amu[o] += __shfl_xor_sync(0xffffffffu, amu[o], s);
            aq [o] += __shfl_xor_sync(0xffffffffu, aq [o], s);
        }
    }
    int warp = tid >> 5, lane = tid & 31;
    if (lane == 0) {
        #pragma unroll
        for (int o = 0; o < DOUT; o++) { redm[warp][o] = amu[o]; redq[warp][o] = aq[o]; }
    }
    __syncthreads();
    if (tid < DOUT) {
        float sm = 0.f, sq = 0.f;
        #pragma unroll
        for (int w = 0; w < 8; w++) { sm += redm[w][tid]; sq += redq[w][tid]; }
        mus[tid] = sm + b_mu2[tid];
        qus[tid] = sq;
    }
    __syncthreads();

    // mid + diag(tr + quad2 + softplus(b_sigma2))  ->  sigma3
    if (tid < DOUT * DOUT) {
        int o = tid / DOUT, p = tid % DOUT;
        float acc = 0.f;
        #pragma unroll 8
        for (int h = 0; h < DH; h++)
            acc += wsm[h * DOUT + o] * s2s[h] * wsm[h * DOUT + p];
        if (o == p) {
            // faithful replication of the reference's flattened-view trace term
            int n  = DOUT * b + o;
            int qn = n >> 8;       // n / 256
            int mn = n & 255;      // n % 256
            float trf = g_Ws2[qn * DH + 2 * mn]     * g_s2[mn * DH + mn]
                      + g_Ws2[qn * DH + 2 * mn + 1] * g_s2[mn * DH + 256 + mn];
            acc += trf + qus[o] + g_spb2[o];
        }
        sig[tid] = acc;
    }
    __syncthreads();

    // softmax (warp 0)
    if (tid < 32) {
        float v = (tid < DOUT) ? mus[tid] : -3.402823466e38f;
        float mx = v;
        #pragma unroll
        for (int s = 16; s; s >>= 1) mx = fmaxf(mx, __shfl_xor_sync(0xffffffffu, mx, s));
        float e = (tid < DOUT) ? expf(v - mx) : 0.f;
        float sm = e;
        #pragma unroll
        for (int s = 16; s; s >>= 1) sm += __shfl_xor_sync(0xffffffffu, sm, s);
        if (tid < DOUT) ps[tid] = e / sm;
    }
    __syncthreads();

    // Sigma_out = J * sigma3 * J^T with J = diag(p) - p p^T, via rank-1 corrections
    if (tid < DOUT) {
        float a = 0.f;
        #pragma unroll
        for (int j = 0; j < DOUT; j++) a += ps[j] * sig[j * DOUT + tid];
        qv[tid] = a;
    }
    __syncthreads();
    if (tid < DOUT * DOUT) {
        int i = tid / DOUT, k = tid % DOUT;
        t1[tid] = ps[i] * (sig[tid] - qv[k]);
    }
    __syncthreads();
    if (tid < DOUT) {
        float a = 0.f;
        #pragma unroll
        for (int k = 0; k < DOUT; k++) a += t1[tid * DOUT + k] * ps[k];
        rr[tid] = a;
    }
    __syncthreads();
    if (tid < DOUT * DOUT) {
        int i = tid / DOUT, l = tid % DOUT;
        out[BATCH * DOUT + b * DOUT * DOUT + tid] = ps[l] * (t1[tid] - rr[i]);
    }
    if (tid < DOUT) out[b * DOUT + tid] = ps[tid];
}

// ---------------- K3: KL finalize ----------------
__global__ void k3_kl(float* __restrict__ out) {
    __shared__ float s[256];
    s[threadIdx.x] = g_klpart[threadIdx.x];
    __syncthreads();
    for (int off = 128; off; off >>= 1) {
        if (threadIdx.x < off) s[threadIdx.x] += s[threadIdx.x + off];
        __syncthreads();
    }
    if (threadIdx.x == 0)
        out[BATCH * DOUT + BATCH * DOUT * DOUT] =
            0.5f * (s[0] - (float)(DH * DIN + DOUT * DH));
}

// ---------------- launch ----------------
extern "C" void kernel_launch(void* const* d_in, const int* in_sizes, int n_in,
                              void* d_out, int out_size) {
    const float* x        = (const float*)d_in[0];
    const float* w_mu1    = (const float*)d_in[1];
    const float* w_sigma1 = (const float*)d_in[2];
    const float* b_mu1    = (const float*)d_in[3];
    const float* b_sigma1 = (const float*)d_in[4];
    const float* w_mu2    = (const float*)d_in[5];
    const float* w_sigma2 = (const float*)d_in[6];
    const float* b_mu2    = (const float*)d_in[7];
    const float* b_sigma2 = (const float*)d_in[8];
    float* out = (float*)d_out;

    k0_prep<<<256, 256>>>(w_mu1, w_sigma1, b_sigma1, w_mu2, w_sigma2, b_sigma2);
    dim3 g1(DH / BN, BATCH / BM, KSPLIT);
    k1_gemm<<<g1, 256>>>(x, w_mu1, w_sigma1);
    k1b_combine<<<(BATCH * DH / 4 + 255) / 256, 256>>>(b_mu1);
    k2_layer2<<<BATCH, 256>>>(w_mu2, b_mu2, out);
    k3_kl<<<1, 256>>>(out);
}